// round 12
// baseline (speedup 1.0000x reference)
#include <cuda_runtime.h>
#include <cstdint>

#define IN_H   1024
#define IN_W   1024
#define OUT_H  256
#define OUT_W  256
#define NTAP   16

#define VCHUNK 8                 // output rows per strip
#define G      4                 // input rows per cp.async group
#define NG     11                // 44 input rows = 11 groups

__device__ __forceinline__ void cp_async16(uint32_t dst_smem, const float* src) {
    asm volatile("cp.async.cg.shared.global [%0], [%1], 16;\n"
                 :: "r"(dst_smem), "l"(src) : "memory");
}
__device__ __forceinline__ void cp_commit() {
    asm volatile("cp.async.commit_group;\n" ::: "memory");
}
template <int N>
__device__ __forceinline__ void cp_wait() {
    asm volatile("cp.async.wait_group %0;\n" :: "n"(N) : "memory");
}

__global__ __launch_bounds__(256, 4)
void bicubic_fused(const float* __restrict__ in, float* __restrict__ out)
{
    constexpr float W[NTAP] = {
        -0.001708984375f, -0.010986328125f, -0.018310546875f, -0.011962890625f,
         0.022705078125f,  0.097412109375f,  0.181884765625f,  0.240966796875f,
         0.240966796875f,  0.181884765625f,  0.097412109375f,  0.022705078125f,
        -0.011962890625f, -0.018310546875f, -0.010986328125f, -0.001708984375f };

    // 48 KB ring; after the V loop it is reinterpreted as v[8][1024] (32 KB)
    __shared__ __align__(16) float ring[3][G][IN_W];
    float (*v)[IN_W] = (float (*)[IN_W])&ring[0][0][0];

    const int tid   = threadIdx.x;               // owns float4 column tid
    const int strip = blockIdx.x;                // 0..31
    const int img   = blockIdx.y;
    const int o0    = strip * VCHUNK;
    const int R0    = 4 * o0 - 6;

    const float* __restrict__ inp  = in  + (size_t)img * (IN_H * IN_W);
    float*       __restrict__ outp = out + ((size_t)img * OUT_H + o0) * OUT_W;

    // per-thread prefetch of group g into ring[g%3] (own 16 B per row)
    auto prefetch = [&](int g) {
#pragma unroll
        for (int r = 0; r < G; ++r) {
            const int gr = min(max(R0 + 4 * g + r, 0), IN_H - 1);
            const uint32_t dst = (uint32_t)__cvta_generic_to_shared(
                &ring[g % 3][r][4 * tid]);
            cp_async16(dst, inp + (size_t)gr * IN_W + 4 * tid);
        }
        cp_commit();
    };

    prefetch(0);
    prefetch(1);

    float4 acc[VCHUNK];
#pragma unroll
    for (int j = 0; j < VCHUNK; ++j) acc[j] = make_float4(0.f, 0.f, 0.f, 0.f);

    // ---- barrier-free V mainloop: thread-private producer/consumer ----
#pragma unroll
    for (int g = 0; g < NG; ++g) {
        if (g < NG - 1) cp_wait<1>(); else cp_wait<0>();

        if (g + 2 < NG) prefetch(g + 2);       // keep 2 groups in flight

        const float4* __restrict__ buf = (const float4*)ring[g % 3];
#pragma unroll
        for (int r = 0; r < G; ++r) {
            const int i = 4 * g + r;
            const float4 x = buf[r * (IN_W / 4) + tid];
#pragma unroll
            for (int j = 0; j < VCHUNK; ++j) {
                const int k = i - 4 * j;               // compile-time pruned
                if (k >= 0 && k < NTAP) {
                    acc[j].x = fmaf(W[k], x.x, acc[j].x);
                    acc[j].y = fmaf(W[k], x.y, acc[j].y);
                    acc[j].z = fmaf(W[k], x.z, acc[j].z);
                    acc[j].w = fmaf(W[k], x.w, acc[j].w);
                }
            }
        }
    }

    // dump acc -> v (each thread overwrites only bytes it staged itself)
#pragma unroll
    for (int j = 0; j < VCHUNK; ++j)
        ((float4*)v[j])[tid] = acc[j];
    __syncthreads();                           // publish v to other threads

    // ---- H phase: 16-tap; center float4 comes from registers (acc) ----
    const int oc = tid;
#pragma unroll
    for (int j = 0; j < VCHUNK; ++j) {
        const float* __restrict__ srow = v[j];
        float r;
        if (oc >= 2 && oc <= 253) {
            const float4* __restrict__ sv = (const float4*)srow + oc;
            const float4 a = sv[-2], b = sv[-1], d = sv[1], e = sv[2];
            const float4 c = acc[j];           // own dump, still in registers
            r = W[0] * a.z;                    // tap 0 = v[4oc-6]
            r = fmaf(W[1],  a.w, r);  r = fmaf(W[2],  b.x, r);
            r = fmaf(W[3],  b.y, r);  r = fmaf(W[4],  b.z, r);
            r = fmaf(W[5],  b.w, r);  r = fmaf(W[6],  c.x, r);
            r = fmaf(W[7],  c.y, r);  r = fmaf(W[8],  c.z, r);
            r = fmaf(W[9],  c.w, r);  r = fmaf(W[10], d.x, r);
            r = fmaf(W[11], d.y, r);  r = fmaf(W[12], d.z, r);
            r = fmaf(W[13], d.w, r);  r = fmaf(W[14], e.x, r);
            r = fmaf(W[15], e.y, r);           // tap 15 = v[4oc+9]
        } else {
            r = 0.f;
#pragma unroll
            for (int k = 0; k < NTAP; ++k)
                r = fmaf(W[k], srow[min(max(4 * oc - 6 + k, 0), IN_W - 1)], r);
        }
        outp[(size_t)j * OUT_W + oc] = r;
    }
}

extern "C" void kernel_launch(void* const* d_in, const int* in_sizes, int n_in,
                              void* d_out, int out_size)
{
    const float* in  = (const float*)d_in[0];
    float*       out = (float*)d_out;

    const int nimg = in_sizes[0] / (IN_H * IN_W);       // 24

    dim3 grid(OUT_H / VCHUNK, nimg);                    // 32 x 24 = 768 blocks
    bicubic_fused<<<grid, 256>>>(in, out);
}

// round 13
// speedup vs baseline: 1.0935x; 1.0935x over previous
#include <cuda_runtime.h>
#include <cstdint>

#define IN_H   1024
#define IN_W   1024
#define OUT_H  256
#define OUT_W  256
#define NTAP   16

#define VCHUNK 8                 // output rows per strip
#define G      4                 // input rows per cp.async group
#define NG     11                // 44 input rows = 11 groups
#define STRIPS 2
#define XBLKS  (OUT_H / VCHUNK / STRIPS)   // 16
#define TOTQ   (STRIPS * NG)               // 22

// dynamic smem: ring[3][G][IN_W] (48 KB) + v4[4][IN_W] (16 KB)
#define SMEM_BYTES ((3*G*IN_W + 4*IN_W) * 4)

__device__ __forceinline__ void cp_async16(uint32_t dst_smem, const float* src) {
    asm volatile("cp.async.cg.shared.global [%0], [%1], 16;\n"
                 :: "r"(dst_smem), "l"(src) : "memory");
}
__device__ __forceinline__ void cp_commit() {
    asm volatile("cp.async.commit_group;\n" ::: "memory");
}
template <int N>
__device__ __forceinline__ void cp_wait() {
    asm volatile("cp.async.wait_group %0;\n" :: "n"(N) : "memory");
}

__global__ __launch_bounds__(256, 3)
void bicubic_fused(const float* __restrict__ in, float* __restrict__ out)
{
    constexpr float W[NTAP] = {
        -0.001708984375f, -0.010986328125f, -0.018310546875f, -0.011962890625f,
         0.022705078125f,  0.097412109375f,  0.181884765625f,  0.240966796875f,
         0.240966796875f,  0.181884765625f,  0.097412109375f,  0.022705078125f,
        -0.011962890625f, -0.018310546875f, -0.010986328125f, -0.001708984375f };

    extern __shared__ __align__(16) float smem[];
    float (*ring)[G][IN_W] = (float (*)[G][IN_W])smem;          // 48 KB
    float (*v4)[IN_W]      = (float (*)[IN_W])(smem + 3 * G * IN_W);  // 16 KB

    const int tid = threadIdx.x;                 // owns float4 column tid
    const int img = blockIdx.y;
    const float* __restrict__ inp = in + (size_t)img * (IN_H * IN_W);

    // issue group q (global counter across both strips) into ring[q%3]
    auto issue = [&](int q) {
        const int s     = q / NG;
        const int g     = q % NG;
        const int strip = blockIdx.x + XBLKS * s;
        const int R0    = 4 * strip * VCHUNK - 6;
#pragma unroll
        for (int r = 0; r < G; ++r) {
            const int gr = min(max(R0 + 4 * g + r, 0), IN_H - 1);
            const uint32_t dst = (uint32_t)__cvta_generic_to_shared(
                &ring[q % 3][r][4 * tid]);
            cp_async16(dst, inp + (size_t)gr * IN_W + 4 * tid);
        }
        cp_commit();
    };

    issue(0);
    issue(1);

#pragma unroll
    for (int it = 0; it < STRIPS; ++it) {
        const int strip = blockIdx.x + XBLKS * it;
        const int o0    = strip * VCHUNK;
        float* __restrict__ outp = out + ((size_t)img * OUT_H + o0) * OUT_W;

        float4 acc[VCHUNK];
#pragma unroll
        for (int j = 0; j < VCHUNK; ++j) acc[j] = make_float4(0.f, 0.f, 0.f, 0.f);

        // ---- barrier-free V mainloop; cp stream continuous across strips ----
#pragma unroll
        for (int g = 0; g < NG; ++g) {
            const int q = it * NG + g;
            if (q + 2 < TOTQ) { issue(q + 2); cp_wait<2>(); }
            else if (q + 1 < TOTQ) cp_wait<1>();
            else cp_wait<0>();

            const float4* __restrict__ buf = (const float4*)ring[q % 3];
#pragma unroll
            for (int r = 0; r < G; ++r) {
                const int i = 4 * g + r;
                const float4 x = buf[r * (IN_W / 4) + tid];
#pragma unroll
                for (int j = 0; j < VCHUNK; ++j) {
                    const int k = i - 4 * j;               // compile-time pruned
                    if (k >= 0 && k < NTAP) {
                        acc[j].x = fmaf(W[k], x.x, acc[j].x);
                        acc[j].y = fmaf(W[k], x.y, acc[j].y);
                        acc[j].z = fmaf(W[k], x.z, acc[j].z);
                        acc[j].w = fmaf(W[k], x.w, acc[j].w);
                    }
                }
            }
        }

        // ---- H phase in two 4-row halves through the 16 KB v4 buffer ----
        const int oc = tid;
#pragma unroll
        for (int h = 0; h < 2; ++h) {
#pragma unroll
            for (int j = 0; j < 4; ++j)
                ((float4*)v4[j])[tid] = acc[4 * h + j];
            __syncthreads();                   // publish half-strip rows

#pragma unroll
            for (int j = 0; j < 4; ++j) {
                const int row = 4 * h + j;
                const float* __restrict__ srow = v4[j];
                float r;
                if (oc >= 2 && oc <= 253) {
                    const float4* __restrict__ sv = (const float4*)srow + oc;
                    const float4 a = sv[-2], b = sv[-1], d = sv[1], e = sv[2];
                    const float4 c = acc[row];   // own dump, still in registers
                    r = W[0] * a.z;              // tap 0 = v[4oc-6]
                    r = fmaf(W[1],  a.w, r);  r = fmaf(W[2],  b.x, r);
                    r = fmaf(W[3],  b.y, r);  r = fmaf(W[4],  b.z, r);
                    r = fmaf(W[5],  b.w, r);  r = fmaf(W[6],  c.x, r);
                    r = fmaf(W[7],  c.y, r);  r = fmaf(W[8],  c.z, r);
                    r = fmaf(W[9],  c.w, r);  r = fmaf(W[10], d.x, r);
                    r = fmaf(W[11], d.y, r);  r = fmaf(W[12], d.z, r);
                    r = fmaf(W[13], d.w, r);  r = fmaf(W[14], e.x, r);
                    r = fmaf(W[15], e.y, r);     // tap 15 = v[4oc+9]
                } else {
                    r = 0.f;
#pragma unroll
                    for (int k = 0; k < NTAP; ++k)
                        r = fmaf(W[k], srow[min(max(4 * oc - 6 + k, 0), IN_W - 1)], r);
                }
                outp[(size_t)row * OUT_W + oc] = r;
            }
            __syncthreads();                   // v4 safe for next half/strip
        }
    }
}

extern "C" void kernel_launch(void* const* d_in, const int* in_sizes, int n_in,
                              void* d_out, int out_size)
{
    const float* in  = (const float*)d_in[0];
    float*       out = (float*)d_out;

    const int nimg = in_sizes[0] / (IN_H * IN_W);       // 24

    cudaFuncSetAttribute(bicubic_fused,
                         cudaFuncAttributeMaxDynamicSharedMemorySize, SMEM_BYTES);

    dim3 grid(XBLKS, nimg);                             // 16 x 24 = 384 blocks
    bicubic_fused<<<grid, 256, SMEM_BYTES>>>(in, out);
}